// round 11
// baseline (speedup 1.0000x reference)
#include <cuda_runtime.h>
#include <cuda_bf16.h>
#include <math.h>
#include <stdint.h>
#include <string.h>

// ---------------- problem dims ----------------
#define BATCH   2
#define LEN     1024
#define DM      1024
#define DI      2048
#define DS      16
#define DTR     64
#define DCONV   4
#define TOK     (BATCH*LEN)
#define DBC_W   96
#define CH      16
#define CLEN    (LEN/CH)
#define SPLITK  8

// ---------------- scratch (device globals) ----------------
__device__ float g_xz [TOK*2*DI];
__device__ float g_uc [TOK*DI];
__device__ float g_dbc[TOK*DBC_W];
__device__ float g_dl [TOK*DI];
__device__ float g_h  [TOK*DM];
__device__ float g_part[SPLITK*TOK*DBC_W];
__device__ float g_sP [BATCH*CH*DI*DS];
__device__ float g_sH [BATCH*CH*DI*DS];
__device__ float g_sS [BATCH*CH*DI*DS];
// bf16 hi/lo activations
__device__ __nv_bfloat16 g_xnh[TOK*DM],   g_xnl[TOK*DM];
__device__ __nv_bfloat16 g_uch[TOK*DI],   g_ucl[TOK*DI];
__device__ __nv_bfloat16 g_dth[TOK*DTR],  g_dtl[TOK*DTR];
__device__ __nv_bfloat16 g_ygh[TOK*DI],   g_ygl[TOK*DI];
__device__ __nv_bfloat16 g_ynh[TOK*DM],   g_ynl[TOK*DM];
__device__ __nv_bfloat16 g_midh[TOK*2*DM],g_midl[TOK*2*DM];
// bf16 hi/lo weights
__device__ __nv_bfloat16 g_w1h[2*DI*DM],  g_w1l[2*DI*DM];
__device__ __nv_bfloat16 g_wxh[128*DI],   g_wxl[128*DI];     // padded 96->128 rows
__device__ __nv_bfloat16 g_wdh[DI*DTR],   g_wdl[DI*DTR];
__device__ __nv_bfloat16 g_woh[DM*DI],    g_wol[DM*DI];
__device__ __nv_bfloat16 g_m1h[2*DM*DM],  g_m1l[2*DM*DM];
__device__ __nv_bfloat16 g_m2h[DM*2*DM],  g_m2l[DM*2*DM];

// ---------------- math helpers ----------------
__device__ __forceinline__ float siluf(float x)    { return x / (1.0f + __expf(-x)); }
__device__ __forceinline__ float softplusf(float x){ return fmaxf(x, 0.0f) + log1pf(expf(-fabsf(x))); }
__device__ __forceinline__ float geluf(float x)    { return 0.5f * x * (1.0f + erff(x * 0.70710678118654752f)); }
__device__ __forceinline__ float warp_sum(float v) {
    #pragma unroll
    for (int o = 16; o > 0; o >>= 1) v += __shfl_xor_sync(0xffffffffu, v, o);
    return v;
}
__device__ __forceinline__ uint32_t pack2(__nv_bfloat16 a, __nv_bfloat16 b) {
    __nv_bfloat162 t; t.x = a; t.y = b;
    uint32_t u; memcpy(&u, &t, 4); return u;
}
__device__ __forceinline__ void split_write(__nv_bfloat16* hi, __nv_bfloat16* lo, size_t idx, float v) {
    __nv_bfloat16 h = __float2bfloat16(v);
    hi[idx] = h;
    lo[idx] = __float2bfloat16(v - __bfloat162float(h));
}

// ---------------- PTX helpers (baseline, compute_103-safe) ----------------
__device__ __forceinline__ uint32_t smem_u32(const void* p) {
    uint32_t a;
    asm("{ .reg .u64 t; cvta.to.shared.u64 t, %1; cvt.u32.u64 %0, t; }" : "=r"(a) : "l"(p));
    return a;
}
__device__ __forceinline__ void mma_bf16(float* c, const uint32_t* a, const uint32_t* b) {
    asm volatile(
        "mma.sync.aligned.m16n8k16.row.col.f32.bf16.bf16.f32 "
        "{%0,%1,%2,%3}, {%4,%5,%6,%7}, {%8,%9}, {%0,%1,%2,%3};"
        : "+f"(c[0]), "+f"(c[1]), "+f"(c[2]), "+f"(c[3])
        : "r"(a[0]), "r"(a[1]), "r"(a[2]), "r"(a[3]), "r"(b[0]), "r"(b[1]));
}
__device__ __forceinline__ void ldsm_x4(uint32_t* r, uint32_t addr) {
    asm volatile("ldmatrix.sync.aligned.m8n8.x4.shared.b16 {%0,%1,%2,%3}, [%4];"
        : "=r"(r[0]), "=r"(r[1]), "=r"(r[2]), "=r"(r[3]) : "r"(addr));
}
__device__ __forceinline__ void cp16(uint32_t dst, const void* src) {
    asm volatile("cp.async.cg.shared.global [%0], [%1], 16;" :: "r"(dst), "l"(src));
}
#define CP_COMMIT() asm volatile("cp.async.commit_group;" ::: "memory")
#define CP_WAIT1()  asm volatile("cp.async.wait_group 1;" ::: "memory")
#define CP_WAIT0()  asm volatile("cp.async.wait_group 0;" ::: "memory")

// ---------------- weight conversion split into 2 kernels (ordering: GEMM = 4th launch) ----------------
__device__ __forceinline__ void cvt_blk(const float* src, __nv_bfloat16* hi, __nv_bfloat16* lo,
                                        int blk, int nreal) {
    int i = (blk * 256 + threadIdx.x) * 4;
    float4 v = (i < nreal) ? *(const float4*)(src + i) : make_float4(0.f,0.f,0.f,0.f);
    __nv_bfloat16 h0 = __float2bfloat16(v.x), h1 = __float2bfloat16(v.y);
    __nv_bfloat16 h2 = __float2bfloat16(v.z), h3 = __float2bfloat16(v.w);
    float l0 = v.x - __bfloat162float(h0), l1 = v.y - __bfloat162float(h1);
    float l2 = v.z - __bfloat162float(h2), l3 = v.w - __bfloat162float(h3);
    *(uint2*)(hi + i) = make_uint2(pack2(h0, h1), pack2(h2, h3));
    *(uint2*)(lo + i) = make_uint2(pack2(__float2bfloat16(l0), __float2bfloat16(l1)),
                                   pack2(__float2bfloat16(l2), __float2bfloat16(l3)));
}
// kernel A: in_proj weights only (4096 blocks)
__global__ __launch_bounds__(256) void cvt_a_k(
    const float* __restrict__ w1, __nv_bfloat16* __restrict__ w1h, __nv_bfloat16* __restrict__ w1l)
{
    cvt_blk(w1, w1h, w1l, blockIdx.x, 2*DI*DM);
}
// kernel B: the rest (256 + 128 + 2048 + 2048 + 2048 = 6528 blocks)
__global__ __launch_bounds__(256) void cvt_b_k(
    const float* __restrict__ wx, const float* __restrict__ wd,
    const float* __restrict__ wo, const float* __restrict__ m1, const float* __restrict__ m2,
    __nv_bfloat16* __restrict__ wxh, __nv_bfloat16* __restrict__ wxl,
    __nv_bfloat16* __restrict__ wdh, __nv_bfloat16* __restrict__ wdl,
    __nv_bfloat16* __restrict__ woh, __nv_bfloat16* __restrict__ wol,
    __nv_bfloat16* __restrict__ m1h, __nv_bfloat16* __restrict__ m1l,
    __nv_bfloat16* __restrict__ m2h, __nv_bfloat16* __restrict__ m2l)
{
    int blk = blockIdx.x;
    if      (blk < 256)   cvt_blk(wx, wxh, wxl, blk,        DBC_W*DI);
    else if (blk < 384)   cvt_blk(wd, wdh, wdl, blk - 256,  DI*DTR);
    else if (blk < 2432)  cvt_blk(wo, woh, wol, blk - 384,  DM*DI);
    else if (blk < 4480)  cvt_blk(m1, m1h, m1l, blk - 2432, 2*DM*DM);
    else                  cvt_blk(m2, m2h, m2l, blk - 4480, DM*2*DM);
}

// ---------------- bf16 MMA GEMM: C = act(A @ W^T + bias) + res ----------------
// 128x128 CTA tile, 8 warps (2x4), warp tile 64x32. KC=64, 3-stage cp.async
// pipeline, ONE __syncthreads per chunk. grid.z = split-K slices.
#define KC    64
#define LDT   72                    // bf16 elems per smem row (144B)
#define TILE_B (128*LDT*2)          // 18432
#define O_AH  0
#define O_AL  (TILE_B)
#define O_BH  (2*TILE_B)
#define O_BL  (3*TILE_B)
#define STG   (4*TILE_B)            // 73728 per stage
#define MG_SMEM (3*STG)             // 221184 (3-stage)

template<int ACT, bool RES, bool WF32, bool WBF16>
__global__ __launch_bounds__(256, 1) void bmma_gemm_k(
    const __nv_bfloat16* __restrict__ Ah, const __nv_bfloat16* __restrict__ Al, int lda,
    const __nv_bfloat16* __restrict__ Bh, const __nv_bfloat16* __restrict__ Bl, int ldw,
    int Nreal, const float* __restrict__ bias,
    const float* __restrict__ res, int ldr,
    float* __restrict__ C, int ldc, size_t pstride,
    __nv_bfloat16* __restrict__ Ch, __nv_bfloat16* __restrict__ Cl, int ldcb,
    int K)
{
    extern __shared__ char smem[];
    const uint32_t sb = smem_u32(smem);
    const int tid  = threadIdx.x;
    const int lane = tid & 31;
    const int wid  = tid >> 5;
    const int wm   = wid & 1;
    const int wn   = wid >> 1;
    const int bm   = blockIdx.y * 128;
    const int bn   = blockIdx.x * 128;
    const int koff = blockIdx.z * K;
    if (WF32) C += (size_t)blockIdx.z * pstride;

    float acc[4][4][4];
    #pragma unroll
    for (int i = 0; i < 4; i++)
        #pragma unroll
        for (int j = 0; j < 4; j++)
            #pragma unroll
            for (int q = 0; q < 4; q++) acc[i][j][q] = 0.f;

    const int NC = K / KC;

    auto issue = [&](int i) {
        const int k0 = koff + i * KC;
        const uint32_t st = sb + (i % 3) * STG;
        #pragma unroll
        for (int it = 0; it < 4; ++it) {
            int idx = tid + (it << 8);          // 0..1023
            int r = idx >> 3, c8 = idx & 7;     // row 0..127, 16B col 0..7
            uint32_t so = (uint32_t)(r * LDT + c8 * 8) * 2;
            size_t ga = (size_t)(bm + r) * lda + k0 + c8 * 8;
            size_t gb = (size_t)(bn + r) * ldw + k0 + c8 * 8;
            cp16(st + O_AH + so, Ah + ga);
            cp16(st + O_AL + so, Al + ga);
            cp16(st + O_BH + so, Bh + gb);
            cp16(st + O_BL + so, Bl + gb);
        }
        CP_COMMIT();
    };

    auto compute = [&](int i) {
        const uint32_t st = sb + (i % 3) * STG;
        const uint32_t sAh = st + O_AH, sAl = st + O_AL;
        const uint32_t sBh = st + O_BH, sBl = st + O_BL;
        #pragma unroll
        for (int kk = 0; kk < KC / 16; ++kk) {
            uint32_t ah[4][4], al[4][4], bh[4][2], bl[4][2];
            const uint32_t acol = kk * 16 + ((lane >> 4) << 3);
            // A fragments: 4x ldmatrix.x4 per hi/lo
            #pragma unroll
            for (int mt = 0; mt < 4; ++mt) {
                uint32_t row = wm * 64 + mt * 16 + (lane & 15);
                uint32_t off = (row * LDT + acol) * 2;
                ldsm_x4(ah[mt], sAh + off);
                ldsm_x4(al[mt], sAl + off);
            }
            // B fragments: 2x ldmatrix.x4 per hi/lo covering nt pairs.
            // lane->matrix mapping: lanes 0-7 -> (nt=2p, col-lo), 8-15 -> (2p, col-hi),
            // 16-23 -> (2p+1, col-lo), 24-31 -> (2p+1, col-hi)
            #pragma unroll
            for (int p = 0; p < 2; ++p) {
                uint32_t row = wn * 32 + p * 16 + ((lane >> 4) << 3) + (lane & 7);
                uint32_t col = kk * 16 + (((lane >> 3) & 1) << 3);
                uint32_t off = (row * LDT + col) * 2;
                uint32_t r4[4];
                ldsm_x4(r4, sBh + off);
                bh[2*p][0] = r4[0]; bh[2*p][1] = r4[1];
                bh[2*p+1][0] = r4[2]; bh[2*p+1][1] = r4[3];
                ldsm_x4(r4, sBl + off);
                bl[2*p][0] = r4[0]; bl[2*p][1] = r4[1];
                bl[2*p+1][0] = r4[2]; bl[2*p+1][1] = r4[3];
            }
            #pragma unroll
            for (int mt = 0; mt < 4; ++mt)
                #pragma unroll
                for (int nt = 0; nt < 4; ++nt) {
                    mma_bf16(acc[mt][nt], ah[mt], bh[nt]);
                    mma_bf16(acc[mt][nt], al[mt], bh[nt]);
                    mma_bf16(acc[mt][nt], ah[mt], bl[nt]);
                }
        }
    };

    issue(0);
    if (NC > 1) issue(1);
    for (int i = 0; i < NC; ++i) {
        if (i + 1 < NC) CP_WAIT1(); else CP_WAIT0();
        __syncthreads();
        compute(i);
        // 3-stage: stage (i+2)%3 is disjoint from stages i%3 / (i+1)%3, and the
        // next iteration's top-of-loop barrier orders everything else.
        if (i + 2 < NC) issue(i + 2);
    }

    // epilogue
    #pragma unroll
    for (int mt = 0; mt < 4; ++mt) {
        #pragma unroll
        for (int nt = 0; nt < 4; ++nt) {
            int m0 = bm + wm * 64 + mt * 16 + (lane >> 2);
            int n0 = bn + wn * 32 + nt * 8 + (lane & 3) * 2;
            if (n0 >= Nreal) continue;
            #pragma unroll
            for (int hf = 0; hf < 2; ++hf) {
                int m = m0 + hf * 8;
                float v0 = acc[mt][nt][hf * 2 + 0];
                float v1 = acc[mt][nt][hf * 2 + 1];
                if (bias) { v0 += bias[n0]; v1 += bias[n0 + 1]; }
                if (ACT == 1) { v0 = softplusf(v0); v1 = softplusf(v1); }
                if (ACT == 2) { v0 = geluf(v0);     v1 = geluf(v1); }
                if (RES) {
                    float2 rv = *(const float2*)(res + (size_t)m * ldr + n0);
                    v0 += rv.x; v1 += rv.y;
                }
                if (WF32)
                    *(float2*)(C + (size_t)m * ldc + n0) = make_float2(v0, v1);
                if (WBF16) {
                    __nv_bfloat16 h0 = __float2bfloat16(v0), h1 = __float2bfloat16(v1);
                    float l0 = v0 - __bfloat162float(h0), l1 = v1 - __bfloat162float(h1);
                    *(uint32_t*)(Ch + (size_t)m * ldcb + n0) = pack2(h0, h1);
                    *(uint32_t*)(Cl + (size_t)m * ldcb + n0) =
                        pack2(__float2bfloat16(l0), __float2bfloat16(l1));
                }
            }
        }
    }
}

// ---------------- split-K reduce for x_proj ----------------
__global__ __launch_bounds__(256) void xproj_reduce_k(
    const float* __restrict__ part, float* __restrict__ dbc,
    __nv_bfloat16* __restrict__ dth, __nv_bfloat16* __restrict__ dtl)
{
    int i = blockIdx.x * 256 + threadIdx.x;
    if (i >= TOK * DBC_W) return;
    float s = 0.f;
    #pragma unroll
    for (int z = 0; z < SPLITK; ++z) s += part[(size_t)z * TOK * DBC_W + i];
    dbc[i] = s;
    int col = i % DBC_W;
    if (col < DTR) {
        int t = i / DBC_W;
        split_write(dth, dtl, (size_t)t * DTR + col, s);
    }
}

// ---------------- layernorm -> bf16 hi/lo ----------------
__global__ __launch_bounds__(256) void layernorm_k(
    const float* __restrict__ x, const float* __restrict__ w,
    const float* __restrict__ b, __nv_bfloat16* __restrict__ oh,
    __nv_bfloat16* __restrict__ ol)
{
    int row = blockIdx.x;
    const float* xr = x + (size_t)row * DM;
    float s = 0.f, s2 = 0.f;
    for (int i = threadIdx.x; i < DM; i += 256) {
        float v = xr[i];
        s += v; s2 += v * v;
    }
    __shared__ float sh1[8], sh2[8];
    int wid = threadIdx.x >> 5, lid = threadIdx.x & 31;
    s = warp_sum(s); s2 = warp_sum(s2);
    if (lid == 0) { sh1[wid] = s; sh2[wid] = s2; }
    __syncthreads();
    if (wid == 0) {
        float a = (lid < 8) ? sh1[lid] : 0.f;
        float c = (lid < 8) ? sh2[lid] : 0.f;
        a = warp_sum(a); c = warp_sum(c);
        if (lid == 0) { sh1[0] = a; sh2[0] = c; }
    }
    __syncthreads();
    float mean = sh1[0] * (1.0f / DM);
    float var  = sh2[0] * (1.0f / DM) - mean * mean;
    float inv  = rsqrtf(var + 1e-5f);
    for (int i = threadIdx.x; i < DM; i += 256)
        split_write(oh, ol, (size_t)row * DM + i, (xr[i] - mean) * inv * w[i] + b[i]);
}

// ---------------- depthwise causal conv + bias + silu (vectorized, t-blocked) ----------------
// thread = (4 consecutive channels) x (8 consecutive tokens): 11 float4 loads -> 8 outputs
#define CTB 8
__global__ __launch_bounds__(256) void conv_silu_k(
    const float* __restrict__ xz, const float* __restrict__ cw,
    const float* __restrict__ cb, float* __restrict__ uc,
    __nv_bfloat16* __restrict__ uch, __nv_bfloat16* __restrict__ ucl)
{
    int g = blockIdx.x * 256 + threadIdx.x;      // over (TOK/CTB)*(DI/4) = 131072
    int dq = g & (DI/4 - 1);                     // 0..511
    int tb = g >> 9;                             // 0..255
    int d  = dq * 4;
    int t0 = tb * CTB;
    int l0 = t0 & (LEN - 1);                     // sequence-local (blocks never straddle batches)

    // weights: per channel c, 4 taps
    float4 wv[4];
    #pragma unroll
    for (int c = 0; c < 4; ++c) wv[c] = *(const float4*)(cw + (d + c) * DCONV);
    float4 bv = *(const float4*)(cb + d);

    // u window: tokens t0-3 .. t0+7 (11 values), zero outside sequence start
    float4 xs[CTB + 3];
    #pragma unroll
    for (int i = 0; i < CTB + 3; ++i) {
        int ls = l0 - 3 + i;
        xs[i] = (ls >= 0) ? *(const float4*)(xz + (size_t)(t0 - 3 + i) * (2 * DI) + d)
                          : make_float4(0.f, 0.f, 0.f, 0.f);
    }

    #pragma unroll
    for (int r = 0; r < CTB; ++r) {
        float a0 = bv.x, a1 = bv.y, a2 = bv.z, a3 = bv.w;
        #pragma unroll
        for (int j = 0; j < DCONV; ++j) {
            float4 u = xs[r + j];
            a0 = fmaf(((const float*)&wv[0])[j], u.x, a0);
            a1 = fmaf(((const float*)&wv[1])[j], u.y, a1);
            a2 = fmaf(((const float*)&wv[2])[j], u.z, a2);
            a3 = fmaf(((const float*)&wv[3])[j], u.w, a3);
        }
        a0 = siluf(a0); a1 = siluf(a1); a2 = siluf(a2); a3 = siluf(a3);
        size_t o = (size_t)(t0 + r) * DI + d;
        *(float4*)(uc + o) = make_float4(a0, a1, a2, a3);
        __nv_bfloat16 h0 = __float2bfloat16(a0), h1 = __float2bfloat16(a1);
        __nv_bfloat16 h2 = __float2bfloat16(a2), h3 = __float2bfloat16(a3);
        *(uint2*)(uch + o) = make_uint2(pack2(h0, h1), pack2(h2, h3));
        *(uint2*)(ucl + o) = make_uint2(
            pack2(__float2bfloat16(a0 - __bfloat162float(h0)), __float2bfloat16(a1 - __bfloat162float(h1))),
            pack2(__float2bfloat16(a2 - __bfloat162float(h2)), __float2bfloat16(a3 - __bfloat162float(h3))));
    }
}

// ---------------- chunked selective scan ----------------
__device__ __forceinline__ bool load_A(const float* __restrict__ A_log, int d, float* Ar) {
    #pragma unroll
    for (int n = 0; n < DS; n++) Ar[n] = -expf(A_log[d * DS + n]);
    bool uni = true;
    #pragma unroll
    for (int n = 1; n < DS; n++)
        if (fabsf(Ar[n] - (float)(n + 1) * Ar[0]) > 1e-4f * fabsf(Ar[n]) + 1e-6f) uni = false;
    return uni;
}

__global__ __launch_bounds__(256) void scan_pass1_k(
    const float* __restrict__ delta, const float* __restrict__ uc,
    const float* __restrict__ dbc, const float* __restrict__ A_log,
    float* __restrict__ sP, float* __restrict__ sH)
{
    int g = blockIdx.x * 256 + threadIdx.x;     // BATCH*CH*DI
    int d  = g & (DI - 1);
    int r  = g >> 11;
    int ch = r & (CH - 1);
    int b  = r >> 4;
    float Ar[DS];
    bool uni = load_A(A_log, d, Ar);
    float h[DS];
    #pragma unroll
    for (int n = 0; n < DS; n++) h[n] = 0.f;
    int t0 = b * LEN + ch * CLEN;
    size_t base = (((size_t)(b * CH + ch) * DI) + d) * DS;

    if (uni) {
        float R = 1.f;
        for (int l = 0; l < CLEN; ++l) {
            int t = t0 + l;
            float dl = delta[(size_t)t * DI + d];
            float u  = uc[(size_t)t * DI + d];
            float du = dl * u;
            const float* BC = dbc + (size_t)t * DBC_W + DTR;
            float r0 = __expf(dl * Ar[0]);
            R *= r0;
            float p = r0;
            #pragma unroll
            for (int n = 0; n < DS; n++) { h[n] = fmaf(p, h[n], du * BC[n]); p *= r0; }
        }
        float p = R;
        #pragma unroll
        for (int n = 0; n < DS; n++) { sP[base + n] = p; p *= R; sH[base + n] = h[n]; }
    } else {
        float P[DS];
        #pragma unroll
        for (int n = 0; n < DS; n++) P[n] = 1.f;
        for (int l = 0; l < CLEN; ++l) {
            int t = t0 + l;
            float dl = delta[(size_t)t * DI + d];
            float u  = uc[(size_t)t * DI + d];
            float du = dl * u;
            const float* BC = dbc + (size_t)t * DBC_W + DTR;
            #pragma unroll
            for (int n = 0; n < DS; n++) {
                float dA = __expf(dl * Ar[n]);
                h[n] = fmaf(dA, h[n], du * BC[n]);
                P[n] *= dA;
            }
        }
        #pragma unroll
        for (int n = 0; n < DS; n++) { sP[base + n] = P[n]; sH[base + n] = h[n]; }
    }
}

__global__ __launch_bounds__(256) void scan_combine_k(
    const float* __restrict__ sP, const float* __restrict__ sH, float* __restrict__ sS)
{
    int g = blockIdx.x * 256 + threadIdx.x;   // BATCH*DI
    int d = g & (DI - 1);
    int b = g >> 11;
    float hr[DS];
    #pragma unroll
    for (int n = 0; n < DS; n++) hr[n] = 0.f;
    for (int ch = 0; ch < CH; ++ch) {
        size_t base = (((size_t)(b * CH + ch) * DI) + d) * DS;
        #pragma unroll
        for (int n = 0; n < DS; n++) {
            sS[base + n] = hr[n];
            hr[n] = fmaf(sP[base + n], hr[n], sH[base + n]);
        }
    }
}

__global__ __launch_bounds__(256) void scan_pass2_k(
    const float* __restrict__ delta, const float* __restrict__ uc,
    const float* __restrict__ dbc, const float* __restrict__ xz,
    const float* __restrict__ A_log, const float* __restrict__ Dp,
    const float* __restrict__ sS,
    __nv_bfloat16* __restrict__ ygh, __nv_bfloat16* __restrict__ ygl)
{
    int g = blockIdx.x * 256 + threadIdx.x;
    int d  = g & (DI - 1);
    int r  = g >> 11;
    int ch = r & (CH - 1);
    int b  = r >> 4;
    float Ar[DS];
    bool uni = load_A(A_log, d, Ar);
    float Dd = Dp[d];
    size_t base = (((size_t)(b * CH + ch) * DI) + d) * DS;
    float h[DS];
    #pragma unroll
    for (int n = 0; n < DS; n++) h[n] = sS[base + n];
    int t0 = b * LEN + ch * CLEN;

    for (int l = 0; l < CLEN; ++l) {
        int t = t0 + l;
        float dl = delta[(size_t)t * DI + d];
        float u  = uc[(size_t)t * DI + d];
        float du = dl * u;
        const float* BC = dbc + (size_t)t * DBC_W + DTR;
        float y = 0.f;
        if (uni) {
            float r0 = __expf(dl * Ar[0]);
            float p = r0;
            #pragma unroll
            for (int n = 0; n < DS; n++) {
                h[n] = fmaf(p, h[n], du * BC[n]);
                y = fmaf(h[n], BC[DS + n], y);
                p *= r0;
            }
        } else {
            #pragma unroll
            for (int n = 0; n < DS; n++) {
                float dA = __expf(dl * Ar[n]);
                h[n] = fmaf(dA, h[n], du * BC[n]);
                y = fmaf(h[n], BC[DS + n], y);
            }
        }
        y = fmaf(u, Dd, y);
        float z = xz[(size_t)t * (2 * DI) + DI + d];
        split_write(ygh, ygl, (size_t)t * DI + d, y * siluf(z));
    }
}

// ---------------- host launch ----------------
static void* symp(const void* s) {
    void* p = nullptr;
    cudaGetSymbolAddress(&p, s);
    return p;
}

extern "C" void kernel_launch(void* const* d_in, const int* in_sizes, int n_in,
                              void* d_out, int out_size)
{
    const float* x         = (const float*)d_in[0];
    const float* ln1_w     = (const float*)d_in[1];
    const float* ln1_b     = (const float*)d_in[2];
    const float* in_proj_w = (const float*)d_in[3];
    const float* conv_w    = (const float*)d_in[4];
    const float* conv_b    = (const float*)d_in[5];
    const float* x_proj_w  = (const float*)d_in[6];
    const float* dt_proj_w = (const float*)d_in[7];
    const float* dt_proj_b = (const float*)d_in[8];
    const float* A_log     = (const float*)d_in[9];
    const float* Dp        = (const float*)d_in[10];
    const float* out_proj_w= (const float*)d_in[11];
    const float* ln2_w     = (const float*)d_in[12];
    const float* ln2_b     = (const float*)d_in[13];
    const float* mlp_w1    = (const float*)d_in[14];
    const float* mlp_b1    = (const float*)d_in[15];
    const float* mlp_w2    = (const float*)d_in[16];
    const float* mlp_b2    = (const float*)d_in[17];
    float* out = (float*)d_out;

    float* xz  = (float*)symp(g_xz);
    float* uc  = (float*)symp(g_uc);
    float* dbc = (float*)symp(g_dbc);
    float* dl  = (float*)symp(g_dl);
    float* hb  = (float*)symp(g_h);
    float* part= (float*)symp(g_part);
    float* sP  = (float*)symp(g_sP);
    float* sH  = (float*)symp(g_sH);
    float* sS  = (float*)symp(g_sS);
    __nv_bfloat16* xnh = (__nv_bfloat16*)symp(g_xnh), *xnl = (__nv_bfloat16*)symp(g_xnl);
    __nv_bfloat16* uch = (__nv_bfloat16*)symp(g_uch), *ucl = (__nv_bfloat16*)symp(g_ucl);
    __nv_bfloat16* dth = (__nv_bfloat16*)symp(g_dth), *dtl = (__nv_bfloat16*)symp(g_dtl);
    __nv_bfloat16* ygh = (__nv_bfloat16*)symp(g_ygh), *ygl = (__nv_bfloat16*)symp(g_ygl);
    __nv_bfloat16* ynh = (__nv_bfloat16*)symp(g_ynh), *ynl = (__nv_bfloat16*)symp(g_ynl);
    __nv_bfloat16* midh= (__nv_bfloat16*)symp(g_midh),*midl= (__nv_bfloat16*)symp(g_midl);
    __nv_bfloat16* w1h = (__nv_bfloat16*)symp(g_w1h), *w1l = (__nv_bfloat16*)symp(g_w1l);
    __nv_bfloat16* wxh = (__nv_bfloat16*)symp(g_wxh), *wxl = (__nv_bfloat16*)symp(g_wxl);
    __nv_bfloat16* wdh = (__nv_bfloat16*)symp(g_wdh), *wdl = (__nv_bfloat16*)symp(g_wdl);
    __nv_bfloat16* woh = (__nv_bfloat16*)symp(g_woh), *wol = (__nv_bfloat16*)symp(g_wol);
    __nv_bfloat16* m1h = (__nv_bfloat16*)symp(g_m1h), *m1l = (__nv_bfloat16*)symp(g_m1l);
    __nv_bfloat16* m2h = (__nv_bfloat16*)symp(g_m2h), *m2l = (__nv_bfloat16*)symp(g_m2l);

    cudaFuncSetAttribute(bmma_gemm_k<0, false, true, false>, cudaFuncAttributeMaxDynamicSharedMemorySize, MG_SMEM);
    cudaFuncSetAttribute(bmma_gemm_k<1, false, true, false>, cudaFuncAttributeMaxDynamicSharedMemorySize, MG_SMEM);
    cudaFuncSetAttribute(bmma_gemm_k<0, true,  true, false>, cudaFuncAttributeMaxDynamicSharedMemorySize, MG_SMEM);
    cudaFuncSetAttribute(bmma_gemm_k<2, false, false, true>, cudaFuncAttributeMaxDynamicSharedMemorySize, MG_SMEM);

    // 0) weight conversion (2 launches; positions in_proj at the profiled 4th slot)
    cvt_a_k<<<4096, 256>>>(in_proj_w, w1h, w1l);
    cvt_b_k<<<6528, 256>>>(x_proj_w, dt_proj_w, out_proj_w, mlp_w1, mlp_w2,
                           wxh, wxl, wdh, wdl, woh, wol, m1h, m1l, m2h, m2l);

    const int MT = TOK / 128;   // 16

    // 1) ln1 -> xn bf16
    layernorm_k<<<TOK, 256>>>(x, ln1_w, ln1_b, xnh, xnl);

    // 2) in_proj: M=2048, N=4096, K=1024 -> xz fp32   [4th launch -> profiled]
    bmma_gemm_k<0, false, true, false><<<dim3(32, MT, 1), 256, MG_SMEM>>>(
        xnh, xnl, DM, w1h, w1l, DM, 4096, nullptr, nullptr, 0,
        xz, 2*DI, 0, nullptr, nullptr, 0, DM);

    // 3) conv + silu -> uc fp32 + bf16
    conv_silu_k<<<(TOK/CTB)*(DI/4)/256, 256>>>(xz, conv_w, conv_b, uc, uch, ucl);

    // 4) x_proj split-K: M=2048, N=96(pad 128), K=2048/8 slices -> partials; reduce
    bmma_gemm_k<0, false, true, false><<<dim3(1, MT, SPLITK), 256, MG_SMEM>>>(
        uch, ucl, DI, wxh, wxl, DI, DBC_W, nullptr, nullptr, 0,
        part, DBC_W, (size_t)TOK*DBC_W, nullptr, nullptr, 0, DI/SPLITK);
    xproj_reduce_k<<<(TOK*DBC_W + 255)/256, 256>>>(part, dbc, dth, dtl);

    // 5) dt_proj + softplus: M=2048, N=2048, K=64 -> dl fp32
    bmma_gemm_k<1, false, true, false><<<dim3(16, MT, 1), 256, MG_SMEM>>>(
        dth, dtl, DTR, wdh, wdl, DTR, DI, dt_proj_b, nullptr, 0,
        dl, DI, 0, nullptr, nullptr, 0, DTR);

    // 6) chunked scan -> yg bf16
    scan_pass1_k<<<(BATCH*CH*DI)/256, 256>>>(dl, uc, dbc, A_log, sP, sH);
    scan_combine_k<<<(BATCH*DI)/256, 256>>>(sP, sH, sS);
    scan_pass2_k<<<(BATCH*CH*DI)/256, 256>>>(dl, uc, dbc, xz, A_log, Dp, sS, ygh, ygl);

    // 7) out_proj + residual x: M=2048, N=1024, K=2048 -> h fp32
    bmma_gemm_k<0, true, true, false><<<dim3(8, MT, 1), 256, MG_SMEM>>>(
        ygh, ygl, DI, woh, wol, DI, DM, nullptr, x, DM,
        hb, DM, 0, nullptr, nullptr, 0, DI);

    // 8) ln2 -> yn bf16
    layernorm_k<<<TOK, 256>>>(hb, ln2_w, ln2_b, ynh, ynl);

    // 9) mlp1 + gelu: M=2048, N=2048, K=1024 -> mid bf16
    bmma_gemm_k<2, false, false, true><<<dim3(16, MT, 1), 256, MG_SMEM>>>(
        ynh, ynl, DM, m1h, m1l, DM, 2*DM, mlp_b1, nullptr, 0,
        nullptr, 0, 0, midh, midl, 2*DM, DM);

    // 10) mlp2 + bias + residual h: M=2048, N=1024, K=2048 -> out fp32
    bmma_gemm_k<0, true, true, false><<<dim3(8, MT, 1), 256, MG_SMEM>>>(
        midh, midl, 2*DM, m2h, m2l, 2*DM, DM, mlp_b2, hb, DM,
        out, DM, 0, nullptr, nullptr, 0, 2*DM);
}

// round 14
// speedup vs baseline: 1.0262x; 1.0262x over previous
#include <cuda_runtime.h>
#include <cuda_bf16.h>
#include <math.h>
#include <stdint.h>
#include <string.h>

// ---------------- problem dims ----------------
#define BATCH   2
#define LEN     1024
#define DM      1024
#define DI      2048
#define DS      16
#define DTR     64
#define DCONV   4
#define TOK     (BATCH*LEN)
#define DBC_W   96
#define CH      16
#define CLEN    (LEN/CH)
#define SPLITK  8

// ---------------- scratch (device globals) ----------------
__device__ float g_xz [TOK*2*DI];
__device__ float g_uc [TOK*DI];
__device__ float g_dbc[TOK*DBC_W];
__device__ float g_dl [TOK*DI];
__device__ float g_h  [TOK*DM];
__device__ float g_part[SPLITK*TOK*DBC_W];
__device__ float g_sP [BATCH*CH*DI*DS];
__device__ float g_sH [BATCH*CH*DI*DS];
__device__ float g_sS [BATCH*CH*DI*DS];
// bf16 hi/lo activations
__device__ __nv_bfloat16 g_xnh[TOK*DM],   g_xnl[TOK*DM];
__device__ __nv_bfloat16 g_uch[TOK*DI],   g_ucl[TOK*DI];
__device__ __nv_bfloat16 g_dth[TOK*DTR],  g_dtl[TOK*DTR];
__device__ __nv_bfloat16 g_ygh[TOK*DI],   g_ygl[TOK*DI];
__device__ __nv_bfloat16 g_ynh[TOK*DM],   g_ynl[TOK*DM];
__device__ __nv_bfloat16 g_midh[TOK*2*DM],g_midl[TOK*2*DM];
// bf16 hi/lo weights
__device__ __nv_bfloat16 g_w1h[2*DI*DM],  g_w1l[2*DI*DM];
__device__ __nv_bfloat16 g_wxh[128*DI],   g_wxl[128*DI];     // padded 96->128 rows
__device__ __nv_bfloat16 g_wdh[DI*DTR],   g_wdl[DI*DTR];
__device__ __nv_bfloat16 g_woh[DM*DI],    g_wol[DM*DI];
__device__ __nv_bfloat16 g_m1h[2*DM*DM],  g_m1l[2*DM*DM];
__device__ __nv_bfloat16 g_m2h[DM*2*DM],  g_m2l[DM*2*DM];

// ---------------- math helpers ----------------
__device__ __forceinline__ float siluf(float x)    { return x / (1.0f + __expf(-x)); }
__device__ __forceinline__ float softplusf(float x){ return fmaxf(x, 0.0f) + log1pf(expf(-fabsf(x))); }
__device__ __forceinline__ float geluf(float x)    { return 0.5f * x * (1.0f + erff(x * 0.70710678118654752f)); }
__device__ __forceinline__ float warp_sum(float v) {
    #pragma unroll
    for (int o = 16; o > 0; o >>= 1) v += __shfl_xor_sync(0xffffffffu, v, o);
    return v;
}
__device__ __forceinline__ uint32_t pack2(__nv_bfloat16 a, __nv_bfloat16 b) {
    __nv_bfloat162 t; t.x = a; t.y = b;
    uint32_t u; memcpy(&u, &t, 4); return u;
}
__device__ __forceinline__ void split_write(__nv_bfloat16* hi, __nv_bfloat16* lo, size_t idx, float v) {
    __nv_bfloat16 h = __float2bfloat16(v);
    hi[idx] = h;
    lo[idx] = __float2bfloat16(v - __bfloat162float(h));
}

// ---------------- PTX helpers (baseline, compute_103-safe) ----------------
__device__ __forceinline__ uint32_t smem_u32(const void* p) {
    uint32_t a;
    asm("{ .reg .u64 t; cvta.to.shared.u64 t, %1; cvt.u32.u64 %0, t; }" : "=r"(a) : "l"(p));
    return a;
}
__device__ __forceinline__ void mma_bf16(float* c, const uint32_t* a, const uint32_t* b) {
    asm volatile(
        "mma.sync.aligned.m16n8k16.row.col.f32.bf16.bf16.f32 "
        "{%0,%1,%2,%3}, {%4,%5,%6,%7}, {%8,%9}, {%0,%1,%2,%3};"
        : "+f"(c[0]), "+f"(c[1]), "+f"(c[2]), "+f"(c[3])
        : "r"(a[0]), "r"(a[1]), "r"(a[2]), "r"(a[3]), "r"(b[0]), "r"(b[1]));
}
__device__ __forceinline__ void ldsm_x4(uint32_t* r, uint32_t addr) {
    asm volatile("ldmatrix.sync.aligned.m8n8.x4.shared.b16 {%0,%1,%2,%3}, [%4];"
        : "=r"(r[0]), "=r"(r[1]), "=r"(r[2]), "=r"(r[3]) : "r"(addr));
}
__device__ __forceinline__ void cp16(uint32_t dst, const void* src) {
    asm volatile("cp.async.cg.shared.global [%0], [%1], 16;" :: "r"(dst), "l"(src));
}
#define CP_COMMIT() asm volatile("cp.async.commit_group;" ::: "memory")
#define CP_WAIT1()  asm volatile("cp.async.wait_group 1;" ::: "memory")
#define CP_WAIT0()  asm volatile("cp.async.wait_group 0;" ::: "memory")

// ---------------- weight conversion split into 2 kernels ----------------
__device__ __forceinline__ void cvt_blk(const float* src, __nv_bfloat16* hi, __nv_bfloat16* lo,
                                        int blk, int nreal) {
    int i = (blk * 256 + threadIdx.x) * 4;
    float4 v = (i < nreal) ? *(const float4*)(src + i) : make_float4(0.f,0.f,0.f,0.f);
    __nv_bfloat16 h0 = __float2bfloat16(v.x), h1 = __float2bfloat16(v.y);
    __nv_bfloat16 h2 = __float2bfloat16(v.z), h3 = __float2bfloat16(v.w);
    float l0 = v.x - __bfloat162float(h0), l1 = v.y - __bfloat162float(h1);
    float l2 = v.z - __bfloat162float(h2), l3 = v.w - __bfloat162float(h3);
    *(uint2*)(hi + i) = make_uint2(pack2(h0, h1), pack2(h2, h3));
    *(uint2*)(lo + i) = make_uint2(pack2(__float2bfloat16(l0), __float2bfloat16(l1)),
                                   pack2(__float2bfloat16(l2), __float2bfloat16(l3)));
}
__global__ __launch_bounds__(256) void cvt_a_k(
    const float* __restrict__ w1, __nv_bfloat16* __restrict__ w1h, __nv_bfloat16* __restrict__ w1l)
{
    cvt_blk(w1, w1h, w1l, blockIdx.x, 2*DI*DM);
}
__global__ __launch_bounds__(256) void cvt_b_k(
    const float* __restrict__ wx, const float* __restrict__ wd,
    const float* __restrict__ wo, const float* __restrict__ m1, const float* __restrict__ m2,
    __nv_bfloat16* __restrict__ wxh, __nv_bfloat16* __restrict__ wxl,
    __nv_bfloat16* __restrict__ wdh, __nv_bfloat16* __restrict__ wdl,
    __nv_bfloat16* __restrict__ woh, __nv_bfloat16* __restrict__ wol,
    __nv_bfloat16* __restrict__ m1h, __nv_bfloat16* __restrict__ m1l,
    __nv_bfloat16* __restrict__ m2h, __nv_bfloat16* __restrict__ m2l)
{
    int blk = blockIdx.x;
    if      (blk < 256)   cvt_blk(wx, wxh, wxl, blk,        DBC_W*DI);
    else if (blk < 384)   cvt_blk(wd, wdh, wdl, blk - 256,  DI*DTR);
    else if (blk < 2432)  cvt_blk(wo, woh, wol, blk - 384,  DM*DI);
    else if (blk < 4480)  cvt_blk(m1, m1h, m1l, blk - 2432, 2*DM*DM);
    else                  cvt_blk(m2, m2h, m2l, blk - 4480, DM*2*DM);
}

// ---------------- bf16 MMA GEMM: C = act(A @ W^T + bias) + res ----------------
// CTA tile 128x64, 256 threads = 8 warps (4x2), warp tile 32x32.
// 2 CTAs/SM (smem 110.6KB, regs <=128) -> 16 warps/SM = 4 warps/SMSP.
// KC=64, 2-stage cp.async pipeline (R6-proven two-barrier form). grid.z = split-K.
#define KC    64
#define LDT   72                      // bf16 elems per smem row (144B)
#define A_TILE (128*LDT*2)            // 18432
#define B_TILE (64*LDT*2)             // 9216
#define O_AH  0
#define O_AL  (A_TILE)                // 18432
#define O_BH  (2*A_TILE)              // 36864
#define O_BL  (2*A_TILE + B_TILE)     // 46080
#define STG   (2*A_TILE + 2*B_TILE)   // 55296 per stage
#define MG_SMEM (2*STG)               // 110592 (2-stage)

template<int ACT, bool RES, bool WF32, bool WBF16>
__global__ __launch_bounds__(256, 2) void bmma_gemm_k(
    const __nv_bfloat16* __restrict__ Ah, const __nv_bfloat16* __restrict__ Al, int lda,
    const __nv_bfloat16* __restrict__ Bh, const __nv_bfloat16* __restrict__ Bl, int ldw,
    int Nreal, const float* __restrict__ bias,
    const float* __restrict__ res, int ldr,
    float* __restrict__ C, int ldc, size_t pstride,
    __nv_bfloat16* __restrict__ Ch, __nv_bfloat16* __restrict__ Cl, int ldcb,
    int K)
{
    extern __shared__ char smem[];
    const uint32_t sb = smem_u32(smem);
    const int tid  = threadIdx.x;
    const int lane = tid & 31;
    const int wid  = tid >> 5;       // 0..7
    const int wm   = wid & 3;        // 32-row block (0..3)
    const int wn   = wid >> 2;       // 32-col block (0..1)
    const int bm   = blockIdx.y * 128;
    const int bn   = blockIdx.x * 64;
    const int koff = blockIdx.z * K;
    if (WF32) C += (size_t)blockIdx.z * pstride;

    float acc[2][4][4];
    #pragma unroll
    for (int i = 0; i < 2; i++)
        #pragma unroll
        for (int j = 0; j < 4; j++)
            #pragma unroll
            for (int q = 0; q < 4; q++) acc[i][j][q] = 0.f;

    const int NC = K / KC;

    auto issue = [&](int i) {
        const int k0 = koff + i * KC;
        const uint32_t st = sb + (i & 1) * STG;
        // A: 128 rows x 64 k-elems -> 1024 16B chunks (hi+lo)
        #pragma unroll
        for (int it = 0; it < 4; ++it) {
            int idx = tid + (it << 8);          // 0..1023
            int r = idx >> 3, c8 = idx & 7;     // row 0..127, 16B col 0..7
            uint32_t so = (uint32_t)(r * LDT + c8 * 8) * 2;
            size_t ga = (size_t)(bm + r) * lda + k0 + c8 * 8;
            cp16(st + O_AH + so, Ah + ga);
            cp16(st + O_AL + so, Al + ga);
        }
        // B: 64 rows x 64 k-elems -> 512 16B chunks (hi+lo)
        #pragma unroll
        for (int it = 0; it < 2; ++it) {
            int idx = tid + (it << 8);          // 0..511
            int r = idx >> 3, c8 = idx & 7;     // row 0..63
            uint32_t so = (uint32_t)(r * LDT + c8 * 8) * 2;
            size_t gb = (size_t)(bn + r) * ldw + k0 + c8 * 8;
            cp16(st + O_BH + so, Bh + gb);
            cp16(st + O_BL + so, Bl + gb);
        }
        CP_COMMIT();
    };

    auto compute = [&](int i) {
        const uint32_t st = sb + (i & 1) * STG;
        const uint32_t sAh = st + O_AH, sAl = st + O_AL;
        const uint32_t sBh = st + O_BH, sBl = st + O_BL;
        #pragma unroll
        for (int kk = 0; kk < KC / 16; ++kk) {
            uint32_t ah[2][4], al[2][4], bh[4][2], bl[4][2];
            const uint32_t acol = kk * 16 + ((lane >> 4) << 3);
            #pragma unroll
            for (int mt = 0; mt < 2; ++mt) {
                uint32_t row = wm * 32 + mt * 16 + (lane & 15);
                uint32_t off = (row * LDT + acol) * 2;
                ldsm_x4(ah[mt], sAh + off);
                ldsm_x4(al[mt], sAl + off);
            }
            // B fragments: 2x ldmatrix.x4 covers nt pairs (lanes 0-7/8-15 -> nt=2p,
            // lanes 16-23/24-31 -> nt=2p+1)
            #pragma unroll
            for (int p = 0; p < 2; ++p) {
                uint32_t row = wn * 32 + p * 16 + ((lane >> 4) << 3) + (lane & 7);
                uint32_t col = kk * 16 + (((lane >> 3) & 1) << 3);
                uint32_t off = (row * LDT + col) * 2;
                uint32_t r4[4];
                ldsm_x4(r4, sBh + off);
                bh[2*p][0] = r4[0]; bh[2*p][1] = r4[1];
                bh[2*p+1][0] = r4[2]; bh[2*p+1][1] = r4[3];
                ldsm_x4(r4, sBl + off);
                bl[2*p][0] = r4[0]; bl[2*p][1] = r4[1];
                bl[2*p+1][0] = r4[2]; bl[2*p+1][1] = r4[3];
            }
            #pragma unroll
            for (int mt = 0; mt < 2; ++mt)
                #pragma unroll
                for (int nt = 0; nt < 4; ++nt) {
                    mma_bf16(acc[mt][nt], ah[mt], bh[nt]);
                    mma_bf16(acc[mt][nt], al[mt], bh[nt]);
                    mma_bf16(acc[mt][nt], ah[mt], bl[nt]);
                }
        }
    };

    issue(0);
    if (NC > 1) issue(1);
    for (int i = 0; i < NC; ++i) {
        if (i + 1 < NC) CP_WAIT1(); else CP_WAIT0();
        __syncthreads();
        compute(i);
        __syncthreads();
        if (i + 2 < NC) issue(i + 2);
    }

    // epilogue
    #pragma unroll
    for (int mt = 0; mt < 2; ++mt) {
        #pragma unroll
        for (int nt = 0; nt < 4; ++nt) {
            int m0 = bm + wm * 32 + mt * 16 + (lane >> 2);
            int n0 = bn + wn * 32 + nt * 8 + (lane & 3) * 2;
            if (n0 >= Nreal) continue;
            #pragma unroll
            for (int hf = 0; hf < 2; ++hf) {
                int m = m0 + hf * 8;
                float v0 = acc[mt][nt][hf * 2 + 0];
                float v1 = acc[mt][nt][hf * 2 + 1];
                if (bias) { v0 += bias[n0]; v1 += bias[n0 + 1]; }
                if (ACT == 1) { v0 = softplusf(v0); v1 = softplusf(v1); }
                if (ACT == 2) { v0 = geluf(v0);     v1 = geluf(v1); }
                if (RES) {
                    float2 rv = *(const float2*)(res + (size_t)m * ldr + n0);
                    v0 += rv.x; v1 += rv.y;
                }
                if (WF32)
                    *(float2*)(C + (size_t)m * ldc + n0) = make_float2(v0, v1);
                if (WBF16) {
                    __nv_bfloat16 h0 = __float2bfloat16(v0), h1 = __float2bfloat16(v1);
                    float l0 = v0 - __bfloat162float(h0), l1 = v1 - __bfloat162float(h1);
                    *(uint32_t*)(Ch + (size_t)m * ldcb + n0) = pack2(h0, h1);
                    *(uint32_t*)(Cl + (size_t)m * ldcb + n0) =
                        pack2(__float2bfloat16(l0), __float2bfloat16(l1));
                }
            }
        }
    }
}

// ---------------- split-K reduce for x_proj ----------------
__global__ __launch_bounds__(256) void xproj_reduce_k(
    const float* __restrict__ part, float* __restrict__ dbc,
    __nv_bfloat16* __restrict__ dth, __nv_bfloat16* __restrict__ dtl)
{
    int i = blockIdx.x * 256 + threadIdx.x;
    if (i >= TOK * DBC_W) return;
    float s = 0.f;
    #pragma unroll
    for (int z = 0; z < SPLITK; ++z) s += part[(size_t)z * TOK * DBC_W + i];
    dbc[i] = s;
    int col = i % DBC_W;
    if (col < DTR) {
        int t = i / DBC_W;
        split_write(dth, dtl, (size_t)t * DTR + col, s);
    }
}

// ---------------- layernorm -> bf16 hi/lo ----------------
__global__ __launch_bounds__(256) void layernorm_k(
    const float* __restrict__ x, const float* __restrict__ w,
    const float* __restrict__ b, __nv_bfloat16* __restrict__ oh,
    __nv_bfloat16* __restrict__ ol)
{
    int row = blockIdx.x;
    const float* xr = x + (size_t)row * DM;
    float s = 0.f, s2 = 0.f;
    for (int i = threadIdx.x; i < DM; i += 256) {
        float v = xr[i];
        s += v; s2 += v * v;
    }
    __shared__ float sh1[8], sh2[8];
    int wid = threadIdx.x >> 5, lid = threadIdx.x & 31;
    s = warp_sum(s); s2 = warp_sum(s2);
    if (lid == 0) { sh1[wid] = s; sh2[wid] = s2; }
    __syncthreads();
    if (wid == 0) {
        float a = (lid < 8) ? sh1[lid] : 0.f;
        float c = (lid < 8) ? sh2[lid] : 0.f;
        a = warp_sum(a); c = warp_sum(c);
        if (lid == 0) { sh1[0] = a; sh2[0] = c; }
    }
    __syncthreads();
    float mean = sh1[0] * (1.0f / DM);
    float var  = sh2[0] * (1.0f / DM) - mean * mean;
    float inv  = rsqrtf(var + 1e-5f);
    for (int i = threadIdx.x; i < DM; i += 256)
        split_write(oh, ol, (size_t)row * DM + i, (xr[i] - mean) * inv * w[i] + b[i]);
}

// ---------------- depthwise causal conv + bias + silu (vectorized, t-blocked) ----------------
#define CTB 8
__global__ __launch_bounds__(256) void conv_silu_k(
    const float* __restrict__ xz, const float* __restrict__ cw,
    const float* __restrict__ cb, float* __restrict__ uc,
    __nv_bfloat16* __restrict__ uch, __nv_bfloat16* __restrict__ ucl)
{
    int g = blockIdx.x * 256 + threadIdx.x;      // over (TOK/CTB)*(DI/4) = 131072
    int dq = g & (DI/4 - 1);
    int tb = g >> 9;
    int d  = dq * 4;
    int t0 = tb * CTB;
    int l0 = t0 & (LEN - 1);

    float4 wv[4];
    #pragma unroll
    for (int c = 0; c < 4; ++c) wv[c] = *(const float4*)(cw + (d + c) * DCONV);
    float4 bv = *(const float4*)(cb + d);

    float4 xs[CTB + 3];
    #pragma unroll
    for (int i = 0; i < CTB + 3; ++i) {
        int ls = l0 - 3 + i;
        xs[i] = (ls >= 0) ? *(const float4*)(xz + (size_t)(t0 - 3 + i) * (2 * DI) + d)
                          : make_float4(0.f, 0.f, 0.f, 0.f);
    }

    #pragma unroll
    for (int r = 0; r < CTB; ++r) {
        float a0 = bv.x, a1 = bv.y, a2 = bv.z, a3 = bv.w;
        #pragma unroll
        for (int j = 0; j < DCONV; ++j) {
            float4 u = xs[r + j];
            a0 = fmaf(((const float*)&wv[0])[j], u.x, a0);
            a1 = fmaf(((const float*)&wv[1])[j], u.y, a1);
            a2 = fmaf(((const float*)&wv[2])[j], u.z, a2);
            a3 = fmaf(((const float*)&wv[3])[j], u.w, a3);
        }
        a0 = siluf(a0); a1 = siluf(a1); a2 = siluf(a2); a3 = siluf(a3);
        size_t o = (size_t)(t0 + r) * DI + d;
        *(float4*)(uc + o) = make_float4(a0, a1, a2, a3);
        __nv_bfloat16 h0 = __float2bfloat16(a0), h1 = __float2bfloat16(a1);
        __nv_bfloat16 h2 = __float2bfloat16(a2), h3 = __float2bfloat16(a3);
        *(uint2*)(uch + o) = make_uint2(pack2(h0, h1), pack2(h2, h3));
        *(uint2*)(ucl + o) = make_uint2(
            pack2(__float2bfloat16(a0 - __bfloat162float(h0)), __float2bfloat16(a1 - __bfloat162float(h1))),
            pack2(__float2bfloat16(a2 - __bfloat162float(h2)), __float2bfloat16(a3 - __bfloat162float(h3))));
    }
}

// ---------------- chunked selective scan ----------------
__device__ __forceinline__ bool load_A(const float* __restrict__ A_log, int d, float* Ar) {
    #pragma unroll
    for (int n = 0; n < DS; n++) Ar[n] = -expf(A_log[d * DS + n]);
    bool uni = true;
    #pragma unroll
    for (int n = 1; n < DS; n++)
        if (fabsf(Ar[n] - (float)(n + 1) * Ar[0]) > 1e-4f * fabsf(Ar[n]) + 1e-6f) uni = false;
    return uni;
}

__global__ __launch_bounds__(256) void scan_pass1_k(
    const float* __restrict__ delta, const float* __restrict__ uc,
    const float* __restrict__ dbc, const float* __restrict__ A_log,
    float* __restrict__ sP, float* __restrict__ sH)
{
    int g = blockIdx.x * 256 + threadIdx.x;     // BATCH*CH*DI
    int d  = g & (DI - 1);
    int r  = g >> 11;
    int ch = r & (CH - 1);
    int b  = r >> 4;
    float Ar[DS];
    bool uni = load_A(A_log, d, Ar);
    float h[DS];
    #pragma unroll
    for (int n = 0; n < DS; n++) h[n] = 0.f;
    int t0 = b * LEN + ch * CLEN;
    size_t base = (((size_t)(b * CH + ch) * DI) + d) * DS;

    if (uni) {
        float R = 1.f;
        for (int l = 0; l < CLEN; ++l) {
            int t = t0 + l;
            float dl = delta[(size_t)t * DI + d];
            float u  = uc[(size_t)t * DI + d];
            float du = dl * u;
            const float* BC = dbc + (size_t)t * DBC_W + DTR;
            float r0 = __expf(dl * Ar[0]);
            R *= r0;
            float p = r0;
            #pragma unroll
            for (int n = 0; n < DS; n++) { h[n] = fmaf(p, h[n], du * BC[n]); p *= r0; }
        }
        float p = R;
        #pragma unroll
        for (int n = 0; n < DS; n++) { sP[base + n] = p; p *= R; sH[base + n] = h[n]; }
    } else {
        float P[DS];
        #pragma unroll
        for (int n = 0; n < DS; n++) P[n] = 1.f;
        for (int l = 0; l < CLEN; ++l) {
            int t = t0 + l;
            float dl = delta[(size_t)t * DI + d];
            float u  = uc[(size_t)t * DI + d];
            float du = dl * u;
            const float* BC = dbc + (size_t)t * DBC_W + DTR;
            #pragma unroll
            for (int n = 0; n < DS; n++) {
                float dA = __expf(dl * Ar[n]);
                h[n] = fmaf(dA, h[n], du * BC[n]);
                P[n] *= dA;
            }
        }
        #pragma unroll
        for (int n = 0; n < DS; n++) { sP[base + n] = P[n]; sH[base + n] = h[n]; }
    }
}

__global__ __launch_bounds__(256) void scan_combine_k(
    const float* __restrict__ sP, const float* __restrict__ sH, float* __restrict__ sS)
{
    int g = blockIdx.x * 256 + threadIdx.x;   // BATCH*DI
    int d = g & (DI - 1);
    int b = g >> 11;
    float hr[DS];
    #pragma unroll
    for (int n = 0; n < DS; n++) hr[n] = 0.f;
    for (int ch = 0; ch < CH; ++ch) {
        size_t base = (((size_t)(b * CH + ch) * DI) + d) * DS;
        #pragma unroll
        for (int n = 0; n < DS; n++) {
            sS[base + n] = hr[n];
            hr[n] = fmaf(sP[base + n], hr[n], sH[base + n]);
        }
    }
}

__global__ __launch_bounds__(256) void scan_pass2_k(
    const float* __restrict__ delta, const float* __restrict__ uc,
    const float* __restrict__ dbc, const float* __restrict__ xz,
    const float* __restrict__ A_log, const float* __restrict__ Dp,
    const float* __restrict__ sS,
    __nv_bfloat16* __restrict__ ygh, __nv_bfloat16* __restrict__ ygl)
{
    int g = blockIdx.x * 256 + threadIdx.x;
    int d  = g & (DI - 1);
    int r  = g >> 11;
    int ch = r & (CH - 1);
    int b  = r >> 4;
    float Ar[DS];
    bool uni = load_A(A_log, d, Ar);
    float Dd = Dp[d];
    size_t base = (((size_t)(b * CH + ch) * DI) + d) * DS;
    float h[DS];
    #pragma unroll
    for (int n = 0; n < DS; n++) h[n] = sS[base + n];
    int t0 = b * LEN + ch * CLEN;

    for (int l = 0; l < CLEN; ++l) {
        int t = t0 + l;
        float dl = delta[(size_t)t * DI + d];
        float u  = uc[(size_t)t * DI + d];
        float du = dl * u;
        const float* BC = dbc + (size_t)t * DBC_W + DTR;
        float y = 0.f;
        if (uni) {
            float r0 = __expf(dl * Ar[0]);
            float p = r0;
            #pragma unroll
            for (int n = 0; n < DS; n++) {
                h[n] = fmaf(p, h[n], du * BC[n]);
                y = fmaf(h[n], BC[DS + n], y);
                p *= r0;
            }
        } else {
            #pragma unroll
            for (int n = 0; n < DS; n++) {
                float dA = __expf(dl * Ar[n]);
                h[n] = fmaf(dA, h[n], du * BC[n]);
                y = fmaf(h[n], BC[DS + n], y);
            }
        }
        y = fmaf(u, Dd, y);
        float z = xz[(size_t)t * (2 * DI) + DI + d];
        split_write(ygh, ygl, (size_t)t * DI + d, y * siluf(z));
    }
}

// ---------------- host launch ----------------
static void* symp(const void* s) {
    void* p = nullptr;
    cudaGetSymbolAddress(&p, s);
    return p;
}

extern "C" void kernel_launch(void* const* d_in, const int* in_sizes, int n_in,
                              void* d_out, int out_size)
{
    const float* x         = (const float*)d_in[0];
    const float* ln1_w     = (const float*)d_in[1];
    const float* ln1_b     = (const float*)d_in[2];
    const float* in_proj_w = (const float*)d_in[3];
    const float* conv_w    = (const float*)d_in[4];
    const float* conv_b    = (const float*)d_in[5];
    const float* x_proj_w  = (const float*)d_in[6];
    const float* dt_proj_w = (const float*)d_in[7];
    const float* dt_proj_b = (const float*)d_in[8];
    const float* A_log     = (const float*)d_in[9];
    const float* Dp        = (const float*)d_in[10];
    const float* out_proj_w= (const float*)d_in[11];
    const float* ln2_w     = (const float*)d_in[12];
    const float* ln2_b     = (const float*)d_in[13];
    const float* mlp_w1    = (const float*)d_in[14];
    const float* mlp_b1    = (const float*)d_in[15];
    const float* mlp_w2    = (const float*)d_in[16];
    const float* mlp_b2    = (const float*)d_in[17];
    float* out = (float*)d_out;

    float* xz  = (float*)symp(g_xz);
    float* uc  = (float*)symp(g_uc);
    float* dbc = (float*)symp(g_dbc);
    float* dl  = (float*)symp(g_dl);
    float* hb  = (float*)symp(g_h);
    float* part= (float*)symp(g_part);
    float* sP  = (float*)symp(g_sP);
    float* sH  = (float*)symp(g_sH);
    float* sS  = (float*)symp(g_sS);
    __nv_bfloat16* xnh = (__nv_bfloat16*)symp(g_xnh), *xnl = (__nv_bfloat16*)symp(g_xnl);
    __nv_bfloat16* uch = (__nv_bfloat16*)symp(g_uch), *ucl = (__nv_bfloat16*)symp(g_ucl);
    __nv_bfloat16* dth = (__nv_bfloat16*)symp(g_dth), *dtl = (__nv_bfloat16*)symp(g_dtl);
    __nv_bfloat16* ygh = (__nv_bfloat16*)symp(g_ygh), *ygl = (__nv_bfloat16*)symp(g_ygl);
    __nv_bfloat16* ynh = (__nv_bfloat16*)symp(g_ynh), *ynl = (__nv_bfloat16*)symp(g_ynl);
    __nv_bfloat16* midh= (__nv_bfloat16*)symp(g_midh),*midl= (__nv_bfloat16*)symp(g_midl);
    __nv_bfloat16* w1h = (__nv_bfloat16*)symp(g_w1h), *w1l = (__nv_bfloat16*)symp(g_w1l);
    __nv_bfloat16* wxh = (__nv_bfloat16*)symp(g_wxh), *wxl = (__nv_bfloat16*)symp(g_wxl);
    __nv_bfloat16* wdh = (__nv_bfloat16*)symp(g_wdh), *wdl = (__nv_bfloat16*)symp(g_wdl);
    __nv_bfloat16* woh = (__nv_bfloat16*)symp(g_woh), *wol = (__nv_bfloat16*)symp(g_wol);
    __nv_bfloat16* m1h = (__nv_bfloat16*)symp(g_m1h), *m1l = (__nv_bfloat16*)symp(g_m1l);
    __nv_bfloat16* m2h = (__nv_bfloat16*)symp(g_m2h), *m2l = (__nv_bfloat16*)symp(g_m2l);

    cudaFuncSetAttribute(bmma_gemm_k<0, false, true, false>, cudaFuncAttributeMaxDynamicSharedMemorySize, MG_SMEM);
    cudaFuncSetAttribute(bmma_gemm_k<1, false, true, false>, cudaFuncAttributeMaxDynamicSharedMemorySize, MG_SMEM);
    cudaFuncSetAttribute(bmma_gemm_k<0, true,  true, false>, cudaFuncAttributeMaxDynamicSharedMemorySize, MG_SMEM);
    cudaFuncSetAttribute(bmma_gemm_k<2, false, false, true>, cudaFuncAttributeMaxDynamicSharedMemorySize, MG_SMEM);

    // 0) weight conversion
    cvt_a_k<<<4096, 256>>>(in_proj_w, w1h, w1l);
    cvt_b_k<<<6528, 256>>>(x_proj_w, dt_proj_w, out_proj_w, mlp_w1, mlp_w2,
                           wxh, wxl, wdh, wdl, woh, wol, m1h, m1l, m2h, m2l);

    const int MT = TOK / 128;   // 16

    // 1) ln1 -> xn bf16
    layernorm_k<<<TOK, 256>>>(x, ln1_w, ln1_b, xnh, xnl);

    // 2) in_proj: M=2048, N=4096, K=1024 -> xz fp32   [4th launch -> profiled]
    bmma_gemm_k<0, false, true, false><<<dim3(4096/64, MT, 1), 256, MG_SMEM>>>(
        xnh, xnl, DM, w1h, w1l, DM, 4096, nullptr, nullptr, 0,
        xz, 2*DI, 0, nullptr, nullptr, 0, DM);

    // 3) conv + silu -> uc fp32 + bf16
    conv_silu_k<<<(TOK/CTB)*(DI/4)/256, 256>>>(xz, conv_w, conv_b, uc, uch, ucl);

    // 4) x_proj split-K: M=2048, N=96(pad 128 -> 2 tiles), K=2048/8 slices; reduce
    bmma_gemm_k<0, false, true, false><<<dim3(2, MT, SPLITK), 256, MG_SMEM>>>(
        uch, ucl, DI, wxh, wxl, DI, DBC_W, nullptr, nullptr, 0,
        part, DBC_W, (size_t)TOK*DBC_W, nullptr, nullptr, 0, DI/SPLITK);
    xproj_reduce_k<<<(TOK*DBC_W + 255)/256, 256>>>(part, dbc, dth, dtl);

    // 5) dt_proj + softplus: M=2048, N=2048, K=64 -> dl fp32
    bmma_gemm_k<1, false, true, false><<<dim3(DI/64, MT, 1), 256, MG_SMEM>>>(
        dth, dtl, DTR, wdh, wdl, DTR, DI, dt_proj_b, nullptr, 0,
        dl, DI, 0, nullptr, nullptr, 0, DTR);

    // 6) chunked scan -> yg bf16
    scan_pass1_k<<<(BATCH*CH*DI)/256, 256>>>(dl, uc, dbc, A_log, sP, sH);
    scan_combine_k<<<(BATCH*DI)/256, 256>>>(sP, sH, sS);
    scan_pass2_k<<<(BATCH*CH*DI)/256, 256>>>(dl, uc, dbc, xz, A_log, Dp, sS, ygh, ygl);

    // 7) out_proj + residual x: M=2048, N=1024, K=2048 -> h fp32
    bmma_gemm_k<0, true, true, false><<<dim3(DM/64, MT, 1), 256, MG_SMEM>>>(
        ygh, ygl, DI, woh, wol, DI, DM, nullptr, x, DM,
        hb, DM, 0, nullptr, nullptr, 0, DI);

    // 8) ln2 -> yn bf16
    layernorm_k<<<TOK, 256>>>(hb, ln2_w, ln2_b, ynh, ynl);

    // 9) mlp1 + gelu: M=2048, N=2048, K=1024 -> mid bf16
    bmma_gemm_k<2, false, false, true><<<dim3(2*DM/64, MT, 1), 256, MG_SMEM>>>(
        ynh, ynl, DM, m1h, m1l, DM, 2*DM, mlp_b1, nullptr, 0,
        nullptr, 0, 0, midh, midl, 2*DM, DM);

    // 10) mlp2 + bias + residual h: M=2048, N=1024, K=2048 -> out fp32
    bmma_gemm_k<0, true, true, false><<<dim3(DM/64, MT, 1), 256, MG_SMEM>>>(
        midh, midl, 2*DM, m2h, m2l, 2*DM, DM, mlp_b2, hb, DM,
        out, DM, 0, nullptr, nullptr, 0, 2*DM);
}